// round 9
// baseline (speedup 1.0000x reference)
#include <cuda_runtime.h>
#include <stdint.h>

// Problem shape (fixed by the dataset)
#define BATCH   8192
#define IN_DIM  4096
#define N_RULES 2048
#define KWORDS  (IN_DIM / 32)    // 128 u32 bit-words along k
#define NSPLIT  32               // k-splits for pack_w partial wany (4 words each)
#define WBLOCKS 1024             // pack_w blocks
#define XROWS   8                // rows per pack_x block

// Scratch (device globals — no allocation allowed)
__device__ uint32_t g_wbitsT[KWORDS * N_RULES];   // TRANSPOSED: [w][r]
__device__ uint32_t g_abits [BATCH  * KWORDS];    // [b][w]
__device__ uint32_t g_wany32[NSPLIT * N_RULES];   // per-split OR of rule words
__device__ uint32_t g_aflag [BATCH];              // 1 if row b has exact x==1.0f
__device__ uint32_t g_rsum  [WBLOCKS];            // per-block OR summary
                                                  // (always written -> no init)

// ---------------------------------------------------------------------------
// Kernel 1: pack W > 0.5 + fused partial wany.
// Each thread: 4 consecutive rules (one float4 column quad) x 8 k-bits
// (quarter word). 4 lanes (sub=0..3) combine a full 32-bit word via shfl_xor.
// 262144 threads / 1024 blocks -> ~50 warps/SM of latency hiding (vs 13 in R8).
// Per load instruction the warp touches 4 full 128B lines (contiguous 8-lane
// runs). sub==0 lanes store coalesced uint4 to the transposed layout.
// ---------------------------------------------------------------------------
__global__ __launch_bounds__(256) void pack_w_kernel(const float* __restrict__ W) {
    __shared__ uint4 sm_red[4][16];
    int tid = threadIdx.x;
    int s   = tid & 3;             // sub-word (8 k-bits)
    int rql = (tid >> 2) & 15;     // rule-quad within block
    int wl  = tid >> 6;            // word within block (0..3)

    int split = blockIdx.x & (NSPLIT - 1);   // w-group
    int rq0   = (blockIdx.x >> 5) * 16;      // rule-quad base
    int rq    = rq0 + rql;                   // [0, 512)
    int w     = split * 4 + wl;              // [0, 128)

    const float4* W4 = reinterpret_cast<const float4*>(W);
    uint32_t p0 = 0, p1 = 0, p2 = 0, p3 = 0;
#pragma unroll
    for (int j = 0; j < 8; j++) {
        float4 v = W4[(size_t)(w * 32 + s * 8 + j) * (N_RULES / 4) + rq];
        uint32_t bit = 1u << (s * 8 + j);
        if (v.x > 0.5f) p0 |= bit;
        if (v.y > 0.5f) p1 |= bit;
        if (v.z > 0.5f) p2 |= bit;
        if (v.w > 0.5f) p3 |= bit;
    }
    // butterfly-OR across the 4 sub lanes -> full 32-bit words
    p0 |= __shfl_xor_sync(0xFFFFFFFFu, p0, 1);
    p0 |= __shfl_xor_sync(0xFFFFFFFFu, p0, 2);
    p1 |= __shfl_xor_sync(0xFFFFFFFFu, p1, 1);
    p1 |= __shfl_xor_sync(0xFFFFFFFFu, p1, 2);
    p2 |= __shfl_xor_sync(0xFFFFFFFFu, p2, 1);
    p2 |= __shfl_xor_sync(0xFFFFFFFFu, p2, 2);
    p3 |= __shfl_xor_sync(0xFFFFFFFFu, p3, 1);
    p3 |= __shfl_xor_sync(0xFFFFFFFFu, p3, 2);

    uint4 words = make_uint4(p0, p1, p2, p3);
    if (s == 0) {
        reinterpret_cast<uint4*>(g_wbitsT + (size_t)w * N_RULES)[rq] = words;
        sm_red[wl][rql] = words;
    }
    __syncthreads();
    if (tid < 16) {
        uint4 o = sm_red[0][tid];
#pragma unroll
        for (int k = 1; k < 4; k++) {
            uint4 v = sm_red[k][tid];
            o.x |= v.x; o.y |= v.y; o.z |= v.z; o.w |= v.w;
        }
        reinterpret_cast<uint4*>(g_wany32 + (size_t)split * N_RULES)[rq0 + tid] = o;
        uint32_t any = __reduce_or_sync(0x0000FFFFu, o.x | o.y | o.z | o.w);
        if (tid == 0) g_rsum[blockIdx.x] = any;   // always written each replay
    }
}

// ---------------------------------------------------------------------------
// Kernel 2: pack x, XROWS rows per block. EARLY EXIT: if every rule is empty
// (all g_rsum == 0), abits/aflag can never be consumed -> skip the 128MB read.
// ---------------------------------------------------------------------------
__global__ __launch_bounds__(256) void pack_x_kernel(const float* __restrict__ x) {
    uint4 rs = reinterpret_cast<const uint4*>(g_rsum)[threadIdx.x];  // 256*4=1024
    if (!__syncthreads_or((rs.x | rs.y | rs.z | rs.w) != 0u)) return;

    __shared__ uint32_t sm_ok[8];
    int wi   = threadIdx.x >> 5;
    int lane = threadIdx.x & 31;

    for (int i = 0; i < XROWS; i++) {
        int b = blockIdx.x * XROWS + i;
        const float* px = x + (size_t)b * IN_DIM + wi * 512;
        uint32_t wrd[16];
        uint32_t ones = 0xFFFFFFFFu;
#pragma unroll
        for (int u = 0; u < 16; u++) {
            float v = px[u * 32 + lane];                // coalesced 128B line
            wrd[u] = __ballot_sync(0xFFFFFFFFu, v != 1.0f);
            ones &= wrd[u];
        }
        if (lane == 0) {
            uint4* q = reinterpret_cast<uint4*>(g_abits + b * KWORDS + wi * 16);
            q[0] = make_uint4(wrd[0],  wrd[1],  wrd[2],  wrd[3]);
            q[1] = make_uint4(wrd[4],  wrd[5],  wrd[6],  wrd[7]);
            q[2] = make_uint4(wrd[8],  wrd[9],  wrd[10], wrd[11]);
            q[3] = make_uint4(wrd[12], wrd[13], wrd[14], wrd[15]);
            sm_ok[wi] = (ones == 0xFFFFFFFFu) ? 1u : 0u;
        }
        __syncthreads();
        if (threadIdx.x == 0) {
            uint32_t a = sm_ok[0] & sm_ok[1] & sm_ok[2] & sm_ok[3] &
                         sm_ok[4] & sm_ok[5] & sm_ok[6] & sm_ok[7];
            g_aflag[b] = a ? 0u : 1u;                   // 1 <=> row has exact 1.0
        }
        __syncthreads();
    }
}

// Rare general path: any weight-selected k with x[b,k] != 1 makes res > 0.
// (wbits is transposed; strided reads are fine on this cold path.)
__device__ __forceinline__ float conj_general(int b, int r) {
    const uint32_t* A = g_abits + b * KWORDS;
    for (int i = 0; i < KWORDS; i++) {
        if (A[i] & g_wbitsT[(size_t)i * N_RULES + r]) return 0.0f;
    }
    return 1.0f;
}

// ---------------------------------------------------------------------------
// Kernel 3: output. Block owns 32 rules x 512 rows: folds the 32 wany
// partials ONCE per block into smem, then streams coalesced float4 writes.
// Grid 64 x 16 = 1024 blocks. aflag/abits read only when group non-empty.
// ---------------------------------------------------------------------------
__global__ __launch_bounds__(256) void out_kernel(float* __restrict__ out) {
    __shared__ __align__(16) float s_val[32];   // aflag==0 answer per rule
    __shared__ uint32_t s_w[32];                // folded wany per rule
    __shared__ uint32_t s_empty;
    int tid = threadIdx.x;
    int rg  = blockIdx.x & 63;                  // rule-group: 32 rules
    int b0  = (blockIdx.x >> 6) * 512;          // row-slice base

    if (tid < 32) {
        int r = rg * 32 + tid;
        uint32_t o = 0;
#pragma unroll
        for (int s = 0; s < NSPLIT; s++) o |= g_wany32[s * N_RULES + r];
        s_w[tid]   = o;
        s_val[tid] = (o == 0u) ? 1.0f : 0.0f;
        uint32_t any = __reduce_or_sync(0xFFFFFFFFu, o);
        if (tid == 0) s_empty = (any == 0u) ? 1u : 0u;
    }
    __syncthreads();

    bool empty  = (s_empty != 0u);
    int  chunk  = tid & 7;                      // float4 chunk within 32 rules
    int  rowoff = tid >> 3;                     // 0..31
    float4 v0 = reinterpret_cast<const float4*>(s_val)[chunk];
    float4* o4 = reinterpret_cast<float4*>(out);

#pragma unroll
    for (int it = 0; it < 16; it++) {
        int b = b0 + it * 32 + rowoff;
        float4 o;
        if (empty || !g_aflag[b]) {
            o = v0;                             // dominant path
        } else {
            int r0 = rg * 32 + chunk * 4;
            o.x = (s_w[chunk*4+0] == 0u) ? 1.0f : conj_general(b, r0 + 0);
            o.y = (s_w[chunk*4+1] == 0u) ? 1.0f : conj_general(b, r0 + 1);
            o.z = (s_w[chunk*4+2] == 0u) ? 1.0f : conj_general(b, r0 + 2);
            o.w = (s_w[chunk*4+3] == 0u) ? 1.0f : conj_general(b, r0 + 3);
        }
        o4[(size_t)b * 512 + rg * 8 + chunk] = o;
    }
}

// ---------------------------------------------------------------------------
extern "C" void kernel_launch(void* const* d_in, const int* in_sizes, int n_in,
                              void* d_out, int out_size) {
    const float* x = (const float*)d_in[0];   // [BATCH, IN_DIM]
    const float* W = (const float*)d_in[1];   // [IN_DIM, N_RULES]
    float* out = (float*)d_out;               // [BATCH, N_RULES]

    (void)in_sizes; (void)n_in; (void)out_size;

    pack_w_kernel<<<WBLOCKS, 256>>>(W);            // 1024 blocks, LDG.128
    pack_x_kernel<<<BATCH / XROWS, 256>>>(x);      // 1024 blocks (early exit)
    out_kernel<<<64 * 16, 256>>>(out);             // 1024 blocks
}